// round 1
// baseline (speedup 1.0000x reference)
#include <cuda_runtime.h>

// CenterLoss: mean over i of ||x_i - centers[labels_i]||^2
// x: [4096, 512] f32, centers: [7001, 512] f32, labels: [4096] i32 -> out: [1] f32

#define BATCH 4096
#define DIM 512
#define VEC (DIM / 4)        // 128 float4 per row
#define NBLK 256
#define SPB (BATCH / NBLK)   // 16 samples per block

__device__ float g_partials[NBLK];
__device__ unsigned int g_count = 0;

__global__ __launch_bounds__(128, 8)
void center_loss_kernel(const float4* __restrict__ x,
                        const float4* __restrict__ c,
                        const int* __restrict__ labels,
                        float* __restrict__ out)
{
    const int t = threadIdx.x;   // 0..127, one float4 lane per thread
    const int b = blockIdx.x;
    const int base = b * SPB;

    // Prefetch all 16 labels (broadcast loads) to maximize MLP on the gathers.
    int labs[SPB];
#pragma unroll
    for (int s = 0; s < SPB; s++) labs[s] = __ldg(&labels[base + s]);

    float acc = 0.0f;
#pragma unroll
    for (int s = 0; s < SPB; s++) {
        const int row = base + s;
        float4 xv = x[row * VEC + t];
        float4 cv = c[labs[s] * VEC + t];
        float d0 = xv.x - cv.x;
        float d1 = xv.y - cv.y;
        float d2 = xv.z - cv.z;
        float d3 = xv.w - cv.w;
        acc = fmaf(d0, d0, acc);
        acc = fmaf(d1, d1, acc);
        acc = fmaf(d2, d2, acc);
        acc = fmaf(d3, d3, acc);
    }

    // Warp reduce
#pragma unroll
    for (int o = 16; o; o >>= 1) acc += __shfl_xor_sync(0xffffffffu, acc, o);

    __shared__ float ws[4];
    __shared__ bool is_last;
    if ((t & 31) == 0) ws[t >> 5] = acc;
    __syncthreads();

    if (t == 0) {
        float p = ws[0] + ws[1] + ws[2] + ws[3];
        g_partials[b] = p;
        __threadfence();
        unsigned int v = atomicAdd(&g_count, 1u);
        is_last = (v == NBLK - 1);
    }
    __syncthreads();

    if (is_last) {
        __threadfence();  // acquire side: make all partials visible
        const volatile float* gp = g_partials;
        float v = gp[t] + gp[t + 128];
#pragma unroll
        for (int o = 16; o; o >>= 1) v += __shfl_xor_sync(0xffffffffu, v, o);
        __shared__ float ws2[4];
        if ((t & 31) == 0) ws2[t >> 5] = v;
        __syncthreads();
        if (t == 0) {
            out[0] = (ws2[0] + ws2[1] + ws2[2] + ws2[3]) * (1.0f / (float)BATCH);
            g_count = 0u;  // self-reset: deterministic state for next replay
        }
    }
}

extern "C" void kernel_launch(void* const* d_in, const int* in_sizes, int n_in,
                              void* d_out, int out_size)
{
    const float4* x = (const float4*)d_in[0];
    const float4* c = (const float4*)d_in[1];
    const int* labels = (const int*)d_in[2];
    float* out = (float*)d_out;
    center_loss_kernel<<<NBLK, 128>>>(x, c, labels, out);
}

// round 2
// speedup vs baseline: 1.0109x; 1.0109x over previous
#include <cuda_runtime.h>

// CenterLoss: mean over i of ||x_i - centers[labels_i]||^2
// x: [4096, 512] f32, centers: [7001, 512] f32, labels: [4096] i32 -> out: [1] f32

#define BATCH 4096
#define DIM 512
#define VEC (DIM / 4)        // 128 float4 per row
#define NBLK 1024
#define SPB (BATCH / NBLK)   // 4 samples per block

__device__ float g_partials[NBLK];
__device__ unsigned int g_count = 0;

__global__ __launch_bounds__(128, 8)
void center_loss_kernel(const float4* __restrict__ x,
                        const float4* __restrict__ c,
                        const int4* __restrict__ labels4,
                        float* __restrict__ out)
{
    const int t = threadIdx.x;   // 0..127, one float4 lane per thread
    const int b = blockIdx.x;
    const int base = b * SPB;

    // One int4 load fetches all 4 labels (broadcast across the block).
    const int4 lv = __ldg(&labels4[b]);
    const int labs[SPB] = { lv.x, lv.y, lv.z, lv.w };

    // Front-batch all 8 float4 loads: 4 x-rows + 4 gathered center rows.
    float4 xv[SPB], cv[SPB];
#pragma unroll
    for (int s = 0; s < SPB; s++) xv[s] = x[(base + s) * VEC + t];
#pragma unroll
    for (int s = 0; s < SPB; s++) cv[s] = c[labs[s] * VEC + t];

    float acc = 0.0f;
#pragma unroll
    for (int s = 0; s < SPB; s++) {
        float d0 = xv[s].x - cv[s].x;
        float d1 = xv[s].y - cv[s].y;
        float d2 = xv[s].z - cv[s].z;
        float d3 = xv[s].w - cv[s].w;
        acc = fmaf(d0, d0, acc);
        acc = fmaf(d1, d1, acc);
        acc = fmaf(d2, d2, acc);
        acc = fmaf(d3, d3, acc);
    }

    // Warp reduce
#pragma unroll
    for (int o = 16; o; o >>= 1) acc += __shfl_xor_sync(0xffffffffu, acc, o);

    __shared__ float ws[4];
    __shared__ bool is_last;
    if ((t & 31) == 0) ws[t >> 5] = acc;
    __syncthreads();

    if (t == 0) {
        float p = ws[0] + ws[1] + ws[2] + ws[3];
        g_partials[b] = p;
        __threadfence();
        unsigned int v = atomicAdd(&g_count, 1u);
        is_last = (v == NBLK - 1);
    }
    __syncthreads();

    if (is_last) {
        __threadfence();  // acquire: make all partials visible
        const volatile float* gp = g_partials;
        float v = 0.0f;
#pragma unroll
        for (int k = 0; k < NBLK / 128; k++) v += gp[t + k * 128];
#pragma unroll
        for (int o = 16; o; o >>= 1) v += __shfl_xor_sync(0xffffffffu, v, o);
        __shared__ float ws2[4];
        if ((t & 31) == 0) ws2[t >> 5] = v;
        __syncthreads();
        if (t == 0) {
            out[0] = (ws2[0] + ws2[1] + ws2[2] + ws2[3]) * (1.0f / (float)BATCH);
            g_count = 0u;  // self-reset: deterministic state for next replay
        }
    }
}

extern "C" void kernel_launch(void* const* d_in, const int* in_sizes, int n_in,
                              void* d_out, int out_size)
{
    const float4* x = (const float4*)d_in[0];
    const float4* c = (const float4*)d_in[1];
    const int4* labels4 = (const int4*)d_in[2];
    float* out = (float*)d_out;
    center_loss_kernel<<<NBLK, 128>>>(x, c, labels4, out);
}

// round 3
// speedup vs baseline: 1.0295x; 1.0185x over previous
#include <cuda_runtime.h>

// CenterLoss: mean over i of ||x_i - centers[labels_i]||^2
//   = mean( ||x_i||^2 + ||c_l||^2 - 2 x_i.c_l )   (reference's own decomposition)
// x: [4096, 512] f32, centers: [7001, 512] f32, labels: [4096] i32 -> out: [1] f32

#define BATCH 4096
#define DIM 512
#define VEC (DIM / 4)        // 128 float4 per row
#define NBLK 1024
#define SPB (BATCH / NBLK)   // 4 samples per block

__device__ float g_partials[NBLK];
__device__ unsigned int g_count = 0;

__global__ __launch_bounds__(128, 8)
void center_loss_kernel(const float4* __restrict__ x,
                        const float4* __restrict__ c,
                        const int4* __restrict__ labels4,
                        float* __restrict__ out)
{
    const int t = threadIdx.x;   // 0..127, one float4 lane per thread
    const int b = blockIdx.x;
    const int base = b * SPB;

    // One int4 load fetches all 4 labels (broadcast across the block).
    const int4 lv = __ldg(&labels4[b]);
    const int labs[SPB] = { lv.x, lv.y, lv.z, lv.w };

    // Decomposed accumulation: every loaded float4 is consumed immediately
    // and independently -> tiny live ranges -> ptxas can front-batch all
    // 9 loads (true MLP ~9) instead of pairing x/c live ranges.
    float axx = 0.0f, acc_ = 0.0f, axc = 0.0f;
#pragma unroll
    for (int s = 0; s < SPB; s++) {
        float4 xv = x[(base + s) * VEC + t];
        axx = fmaf(xv.x, xv.x, axx);
        axx = fmaf(xv.y, xv.y, axx);
        axx = fmaf(xv.z, xv.z, axx);
        axx = fmaf(xv.w, xv.w, axx);
        float4 cv = c[labs[s] * VEC + t];
        acc_ = fmaf(cv.x, cv.x, acc_);
        acc_ = fmaf(cv.y, cv.y, acc_);
        acc_ = fmaf(cv.z, cv.z, acc_);
        acc_ = fmaf(cv.w, cv.w, acc_);
        axc = fmaf(xv.x, cv.x, axc);
        axc = fmaf(xv.y, cv.y, axc);
        axc = fmaf(xv.z, cv.z, axc);
        axc = fmaf(xv.w, cv.w, axc);
    }
    float acc = axx + acc_ - 2.0f * axc;

    // Warp reduce
#pragma unroll
    for (int o = 16; o; o >>= 1) acc += __shfl_xor_sync(0xffffffffu, acc, o);

    __shared__ float ws[4];
    __shared__ bool is_last;
    if ((t & 31) == 0) ws[t >> 5] = acc;
    __syncthreads();

    if (t == 0) {
        float p = ws[0] + ws[1] + ws[2] + ws[3];
        g_partials[b] = p;
        __threadfence();
        unsigned int v = atomicAdd(&g_count, 1u);
        is_last = (v == NBLK - 1);
    }
    __syncthreads();

    if (is_last) {
        __threadfence();  // acquire: make all partials visible
        const volatile float* gp = g_partials;
        float v = 0.0f;
#pragma unroll
        for (int k = 0; k < NBLK / 128; k++) v += gp[t + k * 128];
#pragma unroll
        for (int o = 16; o; o >>= 1) v += __shfl_xor_sync(0xffffffffu, v, o);
        __shared__ float ws2[4];
        if ((t & 31) == 0) ws2[t >> 5] = v;
        __syncthreads();
        if (t == 0) {
            out[0] = (ws2[0] + ws2[1] + ws2[2] + ws2[3]) * (1.0f / (float)BATCH);
            g_count = 0u;  // self-reset: deterministic state for next replay
        }
    }
}

extern "C" void kernel_launch(void* const* d_in, const int* in_sizes, int n_in,
                              void* d_out, int out_size)
{
    const float4* x = (const float4*)d_in[0];
    const float4* c = (const float4*)d_in[1];
    const int4* labels4 = (const int4*)d_in[2];
    float* out = (float*)d_out;
    center_loss_kernel<<<NBLK, 128>>>(x, c, labels4, out);
}